// round 7
// baseline (speedup 1.0000x reference)
#include <cuda_runtime.h>

#define N_MAX 100000
#define E_MAX 1700000
#define CHUNKS 4

// ---------------- static device scratch (referenced directly in kernels) -----
__device__ __align__(16) float g_ta[(size_t)N_MAX * 64];  // t buffer A (GEMM out)
__device__ __align__(16) float g_tb[(size_t)N_MAX * 64];  // t buffer B (GEMM out)
__device__ __align__(16) float g_h[(size_t)N_MAX * 64];   // prop out / GEMM in
__device__ __align__(16) int2  g_meta[E_MAX];  // CSR: (src, w-bits) per edge (by dst)
__device__ int   g_deg[N_MAX];               // in-degree (incl self loop)
__device__ int   g_cur[N_MAX];               // scatter cursors
__device__ int   g_off[N_MAX + 1];           // CSR offsets, block-LOCAL (add g_bsums)
__device__ float g_dinv[N_MAX];              // deg^-1/2
__device__ int   g_bsums[256];               // scan block sums (exclusive)

__device__ __forceinline__ int foff(int i) {   // final CSR offset
    return g_off[i] + g_bsums[i >> 10];
}

// ---------------- streams/events for fork-join + pipelining (pre-baseline) ---
static cudaStream_t g_s2;
static cudaEvent_t  g_evA, g_evB;
static cudaEvent_t  g_evP[4][CHUNKS];   // prop chunk done -> gemm chunk may run
static cudaEvent_t  g_evG[4];           // all gemm chunks of a layer done
static struct SideInit {
    SideInit() {
        cudaStreamCreateWithFlags(&g_s2, cudaStreamNonBlocking);
        cudaEventCreateWithFlags(&g_evA, cudaEventDisableTiming);
        cudaEventCreateWithFlags(&g_evB, cudaEventDisableTiming);
        for (int l = 0; l < 4; ++l) {
            cudaEventCreateWithFlags(&g_evG[l], cudaEventDisableTiming);
            for (int c = 0; c < CHUNKS; ++c)
                cudaEventCreateWithFlags(&g_evP[l][c], cudaEventDisableTiming);
        }
    }
} g_side_init;

// ---------------- graph preprocessing ----------------
__global__ void k_init(int n) {
    int i = blockIdx.x * blockDim.x + threadIdx.x;
    if (i < n) { g_deg[i] = 1; g_cur[i] = 0; }   // deg starts at 1: self loop
}

// edge_index is int32 (JAX x64 disabled downcasts jnp.int64 -> int32)
__global__ void k_count(const int* __restrict__ ei, int E) {
    int e = blockIdx.x * blockDim.x + threadIdx.x;
    if (e < E) atomicAdd(&g_deg[ei[E + e]], 1);
}

// scan of (deg-1) over 1024-elem tiles, shuffle-based, fused dinv computation
__global__ __launch_bounds__(256) void k_scan1(int n) {
    __shared__ int wsum[8];
    int tid = threadIdx.x;
    int base = blockIdx.x * 1024 + tid * 4;
    int v[4];
#pragma unroll
    for (int j = 0; j < 4; j++) {
        int i = base + j;
        int d = (i < n) ? g_deg[i] : 1;
        v[j] = d - 1;
        if (i < n) g_dinv[i] = rsqrtf((float)d);
    }
    int s = v[0] + v[1] + v[2] + v[3];
    int lane = tid & 31, w = tid >> 5;
    int ps = s;
#pragma unroll
    for (int o = 1; o < 32; o <<= 1) {
        int t = __shfl_up_sync(0xffffffffu, ps, o);
        if (lane >= o) ps += t;
    }
    if (lane == 31) wsum[w] = ps;
    __syncthreads();
    if (w == 0) {
        int t = (lane < 8) ? wsum[lane] : 0;
#pragma unroll
        for (int o = 1; o < 8; o <<= 1) {
            int u = __shfl_up_sync(0xffffffffu, t, o);
            if (lane >= o) t += u;
        }
        if (lane < 8) wsum[lane] = t;
    }
    __syncthreads();
    int run = ps - s + (w ? wsum[w - 1] : 0);   // block-local exclusive
#pragma unroll
    for (int j = 0; j < 4; j++) {
        int i = base + j;
        if (i < n) g_off[i] = run;
        else if (i == n) g_off[n] = run;        // sentinel (block-local)
        run += v[j];
    }
    if (tid == 0) g_bsums[blockIdx.x] = wsum[7];
}

__global__ void k_scan2(int nb) {
    __shared__ int sh[256];
    int tid = threadIdx.x;
    int v = (tid < nb) ? g_bsums[tid] : 0;
    sh[tid] = v;
    __syncthreads();
    for (int o = 1; o < 256; o <<= 1) {
        int t = (tid >= o) ? sh[tid - o] : 0;
        __syncthreads();
        sh[tid] += t;
        __syncthreads();
    }
    if (tid < 256) g_bsums[tid] = sh[tid] - v;   // exclusive (idx >= nb also valid)
}

__global__ void k_scatter(const int* __restrict__ ei, int E) {
    int e = blockIdx.x * blockDim.x + threadIdx.x;
    if (e >= E) return;
    int s = ei[e];
    int d = ei[E + e];
    int pos = foff(d) + atomicAdd(&g_cur[d], 1);
    g_meta[pos] = make_int2(s, __float_as_int(g_dinv[s] * g_dinv[d]));
}

// ---------------- packed f32x2 helpers ----------------
__device__ __forceinline__ unsigned long long dup2(float x) {
    unsigned long long r;
    asm("mov.b64 %0, {%1, %1};" : "=l"(r) : "f"(x));
    return r;
}
__device__ __forceinline__ void ffma2(unsigned long long& d,
                                      unsigned long long a, unsigned long long b) {
    asm("fma.rn.f32x2 %0, %1, %2, %0;" : "+l"(d) : "l"(a), "l"(b));
}
__device__ __forceinline__ float2 unpk(unsigned long long v) {
    float2 r;
    asm("mov.b64 {%0, %1}, %2;" : "=f"(r.x), "=f"(r.y) : "l"(v));
    return r;
}

// ---------------- GEMM: t[row0..][64] = A[.,K] @ W[K,64] over a row chunk ----
// A == nullptr -> read g_h. outSel picks g_ta(0)/g_tb(1). 128x64 tile, 256 thr;
// accumulators pair ADJACENT ROWS (direct LDS.64 a-operand). FMA-pipe-bound.
template <int K>
__global__ __launch_bounds__(256) void k_gemm(const float* __restrict__ Ain,
                                              const float* __restrict__ W, int n,
                                              int rowBase, int outSel) {
    const float* A = Ain ? Ain : g_h;
    float* O = outSel ? g_tb : g_ta;
    constexpr int KC = 32;
    constexpr int PF = 2 * KC + 4;                   // 68 floats per pair-row
    __shared__ __align__(16) float Xs[64 * PF];      // [pair][2k + parity]
    __shared__ __align__(16) float Wsh[KC * 64];

    int tid = threadIdx.x;
    int row0 = rowBase + blockIdx.x * 128;
    int tx = tid & 15, ty = tid >> 4;
    int c0 = tx * 4;
    int p0 = ty * 4;                                 // first row-pair

    unsigned long long acc[4][4];                    // [row-pair][col]
#pragma unroll
    for (int i = 0; i < 4; i++)
#pragma unroll
        for (int j = 0; j < 4; j++) acc[i][j] = 0ull;

    for (int kc = 0; kc < K; kc += KC) {
        __syncthreads();
        // X chunk: coalesced float4 loads, pair-interleaved scalar stores
#pragma unroll
        for (int it = 0; it < 4; ++it) {
            int i = tid + it * 256;          // 1024 float4 slots
            int row = i >> 3;
            int k4 = (i & 7) * 4;
            int gr = row0 + row;
            float4 v = make_float4(0.f, 0.f, 0.f, 0.f);
            if (gr < n) v = *(const float4*)&A[(size_t)gr * K + kc + k4];
            int base = (row >> 1) * PF + (row & 1);
            Xs[base + 2 * (k4 + 0)] = v.x;
            Xs[base + 2 * (k4 + 1)] = v.y;
            Xs[base + 2 * (k4 + 2)] = v.z;
            Xs[base + 2 * (k4 + 3)] = v.w;
        }
        // W chunk (contiguous)
#pragma unroll
        for (int it = 0; it < 2; ++it) {
            int i = tid + it * 256;
            *(float4*)&Wsh[i * 4] = *(const float4*)&W[(size_t)kc * 64 + i * 4];
        }
        __syncthreads();

#pragma unroll
        for (int k = 0; k < KC; ++k) {
            float4 wv = *(const float4*)&Wsh[k * 64 + c0];
            unsigned long long w0 = dup2(wv.x), w1 = dup2(wv.y);
            unsigned long long w2 = dup2(wv.z), w3 = dup2(wv.w);
#pragma unroll
            for (int i = 0; i < 4; i++) {
                unsigned long long x2 =
                    *(const unsigned long long*)&Xs[(p0 + i) * PF + 2 * k];
                ffma2(acc[i][0], x2, w0);
                ffma2(acc[i][1], x2, w1);
                ffma2(acc[i][2], x2, w2);
                ffma2(acc[i][3], x2, w3);
            }
        }
    }

#pragma unroll
    for (int i = 0; i < 4; i++) {
        int gr = row0 + (p0 + i) * 2;
        float2 a0 = unpk(acc[i][0]), a1 = unpk(acc[i][1]);
        float2 a2 = unpk(acc[i][2]), a3 = unpk(acc[i][3]);
        if (gr < n)
            *(float4*)&O[(size_t)gr * 64 + c0] = make_float4(a0.x, a1.x, a2.x, a3.x);
        if (gr + 1 < n)
            *(float4*)&O[(size_t)(gr + 1) * 64 + c0] = make_float4(a0.y, a1.y, a2.y, a3.y);
    }
}

// ---------------- propagation over node range [node0, nodeEnd) --------------
// out[d] = sum_{e: dst=d} w_e * t[src_e] + dinv[d]^2 * t[d] (+bias) (+relu)
// inSel picks t = g_ta(0)/g_tb(1); out == nullptr -> write g_h.
__global__ __launch_bounds__(256) void k_prop(float* __restrict__ outp,
                                              const float* __restrict__ bias, int relu,
                                              int node0, int nodeEnd, int inSel) {
    float* out = outp ? outp : g_h;
    const float* t = inSel ? g_tb : g_ta;
    int node = node0 + ((blockIdx.x * blockDim.x + threadIdx.x) >> 5);
    int lane = threadIdx.x & 31;
    if (node >= nodeEnd) return;
    int beg = foff(node), end = foff(node + 1);
    const float* tf = t + 2 * lane;

    float accx = 0.f, accy = 0.f;
    for (int j = beg; j < end; j += 32) {
        int m = end - j;
        if (m > 32) m = 32;
        int s = 0;
        float wv = 0.f;
        if (lane < m) {
            int2 mw = g_meta[j + lane];
            s = mw.x;
            wv = __int_as_float(mw.y);
        }
#pragma unroll 4
        for (int i = 0; i < m; ++i) {
            int si = __shfl_sync(0xffffffffu, s, i);
            float wi = __shfl_sync(0xffffffffu, wv, i);
            float2 v = *(const float2*)(tf + (size_t)si * 64);
            accx = fmaf(wi, v.x, accx);
            accy = fmaf(wi, v.y, accy);
        }
    }
    // self loop
    float dv = g_dinv[node];
    float2 v0 = *(const float2*)(tf + (size_t)node * 64);
    float w0 = dv * dv;
    accx = fmaf(w0, v0.x, accx);
    accy = fmaf(w0, v0.y, accy);
    if (bias) { accx += bias[2 * lane]; accy += bias[2 * lane + 1]; }
    if (relu) { accx = fmaxf(accx, 0.f); accy = fmaxf(accy, 0.f); }
    *(float2*)(out + (size_t)node * 64 + 2 * lane) = make_float2(accx, accy);
}

// ---------------- launch ----------------
extern "C" void kernel_launch(void* const* d_in, const int* in_sizes, int n_in,
                              void* d_out, int out_size) {
    const float* x     = (const float*)d_in[0];
    const int*   ei    = (const int*)d_in[1];     // int32 (JAX x64 disabled)
    const float* W_in  = (const float*)d_in[2];
    const float* b_in  = (const float*)d_in[3];
    const float* W_h   = (const float*)d_in[4];
    const float* b_h   = (const float*)d_in[5];
    const float* W_out = (const float*)d_in[6];

    int n = in_sizes[0] / 128;
    int E = in_sizes[1] / 2;

    int nb1 = (n + 1023) / 1024;
    int gb = (n + 127) / 128;

    // chunk boundaries in units of 128-row GEMM blocks
    int b0[CHUNKS + 1];
    for (int c = 0; c <= CHUNKS; ++c) b0[c] = (int)((long long)gb * c / CHUNKS);

    // Fork: CSR build on side stream, concurrent with first GEMM on main stream.
    cudaEventRecord(g_evA, 0);
    cudaStreamWaitEvent(g_s2, g_evA, 0);
    k_init   <<<(n + 255) / 256, 256, 0, g_s2>>>(n);
    k_count  <<<(E + 255) / 256, 256, 0, g_s2>>>(ei, E);
    k_scan1  <<<nb1, 256, 0, g_s2>>>(n);
    k_scan2  <<<1, 256, 0, g_s2>>>(nb1);
    k_scatter<<<(E + 255) / 256, 256, 0, g_s2>>>(ei, E);
    cudaEventRecord(g_evB, g_s2);

    // layer-1 GEMM (all rows) overlaps the CSR build; writes buffer A
    k_gemm<128><<<gb, 256>>>(x, W_in, n, 0, 0);
    cudaStreamWaitEvent(0, g_evB, 0);            // prop needs CSR too

    // 4 pipelined stages: prop_l chunks (main) feed gemm_{l+1} chunks (side).
    // Buffer ping-pong: props read A,B,A,B; gemms write B,A,B,A.
    const float* bias[4] = { b_in, b_h, b_h + 64, b_h + 128 };
    const int    relu[4] = { 0, 1, 1, 1 };
    const float* Wn[4]   = { W_h, W_h + 4096, W_h + 8192, W_out };
    for (int l = 0; l < 4; ++l) {
        int inSel = l & 1, outSel = (l + 1) & 1;
        for (int c = 0; c < CHUNKS; ++c) {
            int node0 = b0[c] * 128;
            int nodeEnd = b0[c + 1] * 128; if (nodeEnd > n) nodeEnd = n;
            int nn = nodeEnd - node0;
            k_prop<<<(nn + 7) / 8, 256>>>(nullptr, bias[l], relu[l],
                                          node0, nodeEnd, inSel);
            cudaEventRecord(g_evP[l][c], 0);
            cudaStreamWaitEvent(g_s2, g_evP[l][c], 0);
            k_gemm<64><<<b0[c + 1] - b0[c], 256, 0, g_s2>>>(nullptr, Wn[l], n,
                                                            node0, outSel);
        }
        cudaEventRecord(g_evG[l], g_s2);
        cudaStreamWaitEvent(0, g_evG[l], 0);     // next prop needs all gemm chunks
    }

    // final prop: reads buffer A (g5 output), writes d_out
    k_prop<<<(n + 7) / 8, 256>>>((float*)d_out, nullptr, 0, 0, n, 0);
}

// round 8
// speedup vs baseline: 1.2199x; 1.2199x over previous
#include <cuda_runtime.h>
#include <cuda_fp16.h>

#define N_MAX 100000
#define E_MAX 1700000

// ---------------- static device scratch (referenced directly in kernels) -----
__device__ __align__(16) __half g_t[(size_t)N_MAX * 64];  // GEMM out / prop in (fp16!)
__device__ __align__(16) float  g_h[(size_t)N_MAX * 64];  // prop out / GEMM in (fp32)
__device__ __align__(16) int2   g_meta[E_MAX];  // CSR: (src, w-bits) per edge (by dst)
__device__ int   g_deg[N_MAX];               // in-degree (incl self loop)
__device__ int   g_cur[N_MAX];               // scatter cursors
__device__ int   g_off[N_MAX + 1];           // CSR offsets, block-LOCAL (add g_bsums)
__device__ float g_dinv[N_MAX];              // deg^-1/2
__device__ int   g_bsums[256];               // scan block sums (exclusive)

__device__ __forceinline__ int foff(int i) {   // final CSR offset
    return g_off[i] + g_bsums[i >> 10];
}

// ---------------- side stream for fork-join overlap (created pre-baseline) ---
static cudaStream_t g_s2;
static cudaEvent_t  g_evA, g_evB;
static struct SideInit {
    SideInit() {
        cudaStreamCreateWithFlags(&g_s2, cudaStreamNonBlocking);
        cudaEventCreateWithFlags(&g_evA, cudaEventDisableTiming);
        cudaEventCreateWithFlags(&g_evB, cudaEventDisableTiming);
    }
} g_side_init;

// ---------------- graph preprocessing ----------------
__global__ void k_init(int n) {
    int i = blockIdx.x * blockDim.x + threadIdx.x;
    if (i < n) { g_deg[i] = 1; g_cur[i] = 0; }   // deg starts at 1: self loop
}

// edge_index is int32 (JAX x64 disabled downcasts jnp.int64 -> int32)
__global__ void k_count(const int* __restrict__ ei, int E) {
    int e = blockIdx.x * blockDim.x + threadIdx.x;
    if (e < E) atomicAdd(&g_deg[ei[E + e]], 1);
}

// scan of (deg-1) over 1024-elem tiles, shuffle-based, fused dinv computation
__global__ __launch_bounds__(256) void k_scan1(int n) {
    __shared__ int wsum[8];
    int tid = threadIdx.x;
    int base = blockIdx.x * 1024 + tid * 4;
    int v[4];
#pragma unroll
    for (int j = 0; j < 4; j++) {
        int i = base + j;
        int d = (i < n) ? g_deg[i] : 1;
        v[j] = d - 1;
        if (i < n) g_dinv[i] = rsqrtf((float)d);
    }
    int s = v[0] + v[1] + v[2] + v[3];
    int lane = tid & 31, w = tid >> 5;
    int ps = s;
#pragma unroll
    for (int o = 1; o < 32; o <<= 1) {
        int t = __shfl_up_sync(0xffffffffu, ps, o);
        if (lane >= o) ps += t;
    }
    if (lane == 31) wsum[w] = ps;
    __syncthreads();
    if (w == 0) {
        int t = (lane < 8) ? wsum[lane] : 0;
#pragma unroll
        for (int o = 1; o < 8; o <<= 1) {
            int u = __shfl_up_sync(0xffffffffu, t, o);
            if (lane >= o) t += u;
        }
        if (lane < 8) wsum[lane] = t;
    }
    __syncthreads();
    int run = ps - s + (w ? wsum[w - 1] : 0);   // block-local exclusive
#pragma unroll
    for (int j = 0; j < 4; j++) {
        int i = base + j;
        if (i < n) g_off[i] = run;
        else if (i == n) g_off[n] = run;        // sentinel (block-local)
        run += v[j];
    }
    if (tid == 0) g_bsums[blockIdx.x] = wsum[7];
}

__global__ void k_scan2(int nb) {
    __shared__ int sh[256];
    int tid = threadIdx.x;
    int v = (tid < nb) ? g_bsums[tid] : 0;
    sh[tid] = v;
    __syncthreads();
    for (int o = 1; o < 256; o <<= 1) {
        int t = (tid >= o) ? sh[tid - o] : 0;
        __syncthreads();
        sh[tid] += t;
        __syncthreads();
    }
    if (tid < 256) g_bsums[tid] = sh[tid] - v;   // exclusive (idx >= nb also valid)
}

__global__ void k_scatter(const int* __restrict__ ei, int E) {
    int e = blockIdx.x * blockDim.x + threadIdx.x;
    if (e >= E) return;
    int s = ei[e];
    int d = ei[E + e];
    int pos = foff(d) + atomicAdd(&g_cur[d], 1);
    g_meta[pos] = make_int2(s, __float_as_int(g_dinv[s] * g_dinv[d]));
}

// ---------------- packed f32x2 helpers ----------------
__device__ __forceinline__ unsigned long long dup2(float x) {
    unsigned long long r;
    asm("mov.b64 %0, {%1, %1};" : "=l"(r) : "f"(x));
    return r;
}
__device__ __forceinline__ void ffma2(unsigned long long& d,
                                      unsigned long long a, unsigned long long b) {
    asm("fma.rn.f32x2 %0, %1, %2, %0;" : "+l"(d) : "l"(a), "l"(b));
}
__device__ __forceinline__ float2 unpk(unsigned long long v) {
    float2 r;
    asm("mov.b64 {%0, %1}, %2;" : "=f"(r.x), "=f"(r.y) : "l"(v));
    return r;
}

// ---------------- GEMM: g_t[n,64](fp16) = A[n,K](fp32) @ W[K,64] -------------
// A == nullptr -> read g_h. 128x64 tile, 256 thr; accumulators pair ADJACENT
// ROWS (direct LDS.64 a-operand, fp32 math); epilogue converts to fp16.
template <int K>
__global__ __launch_bounds__(256) void k_gemm(const float* __restrict__ Ain,
                                              const float* __restrict__ W, int n) {
    const float* A = Ain ? Ain : g_h;
    constexpr int KC = 32;
    constexpr int PF = 2 * KC + 4;                   // 68 floats per pair-row
    __shared__ __align__(16) float Xs[64 * PF];      // [pair][2k + parity]
    __shared__ __align__(16) float Wsh[KC * 64];

    int tid = threadIdx.x;
    int row0 = blockIdx.x * 128;
    int tx = tid & 15, ty = tid >> 4;
    int c0 = tx * 4;
    int p0 = ty * 4;                                 // first row-pair

    unsigned long long acc[4][4];                    // [row-pair][col]
#pragma unroll
    for (int i = 0; i < 4; i++)
#pragma unroll
        for (int j = 0; j < 4; j++) acc[i][j] = 0ull;

    for (int kc = 0; kc < K; kc += KC) {
        __syncthreads();
        // X chunk: coalesced float4 loads, pair-interleaved scalar stores
#pragma unroll
        for (int it = 0; it < 4; ++it) {
            int i = tid + it * 256;          // 1024 float4 slots
            int row = i >> 3;
            int k4 = (i & 7) * 4;
            int gr = row0 + row;
            float4 v = make_float4(0.f, 0.f, 0.f, 0.f);
            if (gr < n) v = *(const float4*)&A[(size_t)gr * K + kc + k4];
            int base = (row >> 1) * PF + (row & 1);
            Xs[base + 2 * (k4 + 0)] = v.x;
            Xs[base + 2 * (k4 + 1)] = v.y;
            Xs[base + 2 * (k4 + 2)] = v.z;
            Xs[base + 2 * (k4 + 3)] = v.w;
        }
        // W chunk (contiguous)
#pragma unroll
        for (int it = 0; it < 2; ++it) {
            int i = tid + it * 256;
            *(float4*)&Wsh[i * 4] = *(const float4*)&W[(size_t)kc * 64 + i * 4];
        }
        __syncthreads();

#pragma unroll
        for (int k = 0; k < KC; ++k) {
            float4 wv = *(const float4*)&Wsh[k * 64 + c0];
            unsigned long long w0 = dup2(wv.x), w1 = dup2(wv.y);
            unsigned long long w2 = dup2(wv.z), w3 = dup2(wv.w);
#pragma unroll
            for (int i = 0; i < 4; i++) {
                unsigned long long x2 =
                    *(const unsigned long long*)&Xs[(p0 + i) * PF + 2 * k];
                ffma2(acc[i][0], x2, w0);
                ffma2(acc[i][1], x2, w1);
                ffma2(acc[i][2], x2, w2);
                ffma2(acc[i][3], x2, w3);
            }
        }
    }

#pragma unroll
    for (int i = 0; i < 4; i++) {
        int gr = row0 + (p0 + i) * 2;
        float2 a0 = unpk(acc[i][0]), a1 = unpk(acc[i][1]);
        float2 a2 = unpk(acc[i][2]), a3 = unpk(acc[i][3]);
        if (gr < n) {
            __half2 h01 = __floats2half2_rn(a0.x, a1.x);
            __half2 h23 = __floats2half2_rn(a2.x, a3.x);
            *(uint2*)&g_t[(size_t)gr * 64 + c0] =
                make_uint2(*(unsigned*)&h01, *(unsigned*)&h23);
        }
        if (gr + 1 < n) {
            __half2 h01 = __floats2half2_rn(a0.y, a1.y);
            __half2 h23 = __floats2half2_rn(a2.y, a3.y);
            *(uint2*)&g_t[(size_t)(gr + 1) * 64 + c0] =
                make_uint2(*(unsigned*)&h01, *(unsigned*)&h23);
        }
    }
}

// ---------------- propagation: out[d] = sum_{e: dst=d} w_e * t[src_e]
//                   + dinv[d]^2 * t[d] (+bias) (+relu), t in fp16 -------------
// out == nullptr -> write g_h (fp32). Warp per node, lane owns 2 features
// (one half2), fp32 register accumulation, packed CSR meta via LDG.64+shuffle.
__global__ __launch_bounds__(256) void k_prop(float* __restrict__ outp,
                                              const float* __restrict__ bias, int relu,
                                              int n) {
    float* out = outp ? outp : g_h;
    const __half2* t2 = (const __half2*)g_t;     // row = 32 half2
    int node = (blockIdx.x * blockDim.x + threadIdx.x) >> 5;
    int lane = threadIdx.x & 31;
    if (node >= n) return;
    int beg = foff(node), end = foff(node + 1);
    const __half2* tf = t2 + lane;

    float accx = 0.f, accy = 0.f;
    for (int j = beg; j < end; j += 32) {
        int m = end - j;
        if (m > 32) m = 32;
        int s = 0;
        float wv = 0.f;
        if (lane < m) {
            int2 mw = g_meta[j + lane];
            s = mw.x;
            wv = __int_as_float(mw.y);
        }
#pragma unroll 4
        for (int i = 0; i < m; ++i) {
            int si = __shfl_sync(0xffffffffu, s, i);
            float wi = __shfl_sync(0xffffffffu, wv, i);
            float2 v = __half22float2(tf[(size_t)si * 32]);
            accx = fmaf(wi, v.x, accx);
            accy = fmaf(wi, v.y, accy);
        }
    }
    // self loop
    float dv = g_dinv[node];
    float2 v0 = __half22float2(tf[(size_t)node * 32]);
    float w0 = dv * dv;
    accx = fmaf(w0, v0.x, accx);
    accy = fmaf(w0, v0.y, accy);
    if (bias) { accx += bias[2 * lane]; accy += bias[2 * lane + 1]; }
    if (relu) { accx = fmaxf(accx, 0.f); accy = fmaxf(accy, 0.f); }
    *(float2*)(out + (size_t)node * 64 + 2 * lane) = make_float2(accx, accy);
}

// ---------------- launch ----------------
extern "C" void kernel_launch(void* const* d_in, const int* in_sizes, int n_in,
                              void* d_out, int out_size) {
    const float* x     = (const float*)d_in[0];
    const int*   ei    = (const int*)d_in[1];     // int32 (JAX x64 disabled)
    const float* W_in  = (const float*)d_in[2];
    const float* b_in  = (const float*)d_in[3];
    const float* W_h   = (const float*)d_in[4];
    const float* b_h   = (const float*)d_in[5];
    const float* W_out = (const float*)d_in[6];

    int n = in_sizes[0] / 128;
    int E = in_sizes[1] / 2;

    int nb1 = (n + 1023) / 1024;
    int gb = (n + 127) / 128;
    int pb = (n + 7) / 8;

    // Fork: CSR build on side stream, concurrent with first GEMM on main stream.
    cudaEventRecord(g_evA, 0);
    cudaStreamWaitEvent(g_s2, g_evA, 0);
    k_init   <<<(n + 255) / 256, 256, 0, g_s2>>>(n);
    k_count  <<<(E + 255) / 256, 256, 0, g_s2>>>(ei, E);
    k_scan1  <<<nb1, 256, 0, g_s2>>>(n);
    k_scan2  <<<1, 256, 0, g_s2>>>(nb1);
    k_scatter<<<(E + 255) / 256, 256, 0, g_s2>>>(ei, E);
    cudaEventRecord(g_evB, g_s2);

    // layer 1 GEMM overlaps the CSR build
    k_gemm<128><<<gb, 256>>>(x, W_in, n);

    // Join: prop needs both GEMM output and CSR
    cudaStreamWaitEvent(0, g_evB, 0);
    k_prop<<<pb, 256>>>(nullptr, b_in, 0, n);

    // hidden layers: h = relu(prop(h @ W_h[l]) + b_h[l])
    for (int l = 0; l < 3; ++l) {
        k_gemm<64><<<gb, 256>>>(nullptr, W_h + (size_t)l * 64 * 64, n);
        k_prop<<<pb, 256>>>(nullptr, b_h + (size_t)l * 64, 1, n);
    }

    // output layer: out = prop(h @ W_out), no bias, no relu
    k_gemm<64><<<gb, 256>>>(nullptr, W_out, n);
    k_prop<<<pb, 256>>>((float*)d_out, nullptr, 0, n);
}

// round 10
// speedup vs baseline: 1.2331x; 1.0108x over previous
#include <cuda_runtime.h>
#include <cuda_fp16.h>

#define N_MAX 100000
#define E_MAX 1700000

// ---------------- static device scratch (zero-initialized; k_reset re-zeroes
// the atomically-accumulated ones at the END of each replay) -----------------
__device__ __align__(16) __half g_t[(size_t)N_MAX * 64];  // GEMM out / prop in (fp16)
__device__ __align__(16) float  g_h[(size_t)N_MAX * 64];  // prop out / GEMM in (fp32)
__device__ __align__(16) int2   g_meta[E_MAX];  // CSR: (src, w-bits) per edge (by dst)
__device__ int   g_deg[N_MAX];               // RAW in-degree (no self loop); zero-init
__device__ int   g_cur[N_MAX];               // scatter cursors; zero-init
__device__ int   g_off[N_MAX + 1];           // CSR offsets, block-LOCAL (add g_bsums)
__device__ float g_dinv[N_MAX];              // (deg+1)^-1/2
__device__ int   g_bsums[256];               // scan block sums (exclusive after scan1f)
__device__ int   g_done;                     // scan1f completion counter (self-reset)

__device__ __forceinline__ int foff(int i) {   // final CSR offset
    return g_off[i] + g_bsums[i >> 10];
}

// ---------------- side stream for fork-join overlap (created pre-baseline) ---
static cudaStream_t g_s2;
static cudaEvent_t  g_evA, g_evB, g_evC;
static struct SideInit {
    SideInit() {
        cudaStreamCreateWithFlags(&g_s2, cudaStreamNonBlocking);
        cudaEventCreateWithFlags(&g_evA, cudaEventDisableTiming);
        cudaEventCreateWithFlags(&g_evB, cudaEventDisableTiming);
        cudaEventCreateWithFlags(&g_evC, cudaEventDisableTiming);
    }
} g_side_init;

// ---------------- graph preprocessing ----------------
// edge_index is int32 (JAX x64 disabled downcasts jnp.int64 -> int32)
__global__ void k_count(const int* __restrict__ ei, int E) {
    int e = blockIdx.x * blockDim.x + threadIdx.x;
    if (e < E) atomicAdd(&g_deg[ei[E + e]], 1);
}

// scan of raw deg over 1024-elem tiles + fused dinv; LAST finishing block also
// performs the cross-block scan of g_bsums (replaces the old k_scan2 launch).
__global__ __launch_bounds__(256) void k_scan1f(int n, int nb) {
    __shared__ int wsum[8];
    __shared__ int sh[256];
    __shared__ int isLast;
    int tid = threadIdx.x;
    int base = blockIdx.x * 1024 + tid * 4;
    int v[4];
#pragma unroll
    for (int j = 0; j < 4; j++) {
        int i = base + j;
        int draw = (i < n) ? g_deg[i] : 0;       // raw edge count (excl self)
        v[j] = draw;
        if (i < n) g_dinv[i] = rsqrtf((float)(draw + 1));
    }
    int s = v[0] + v[1] + v[2] + v[3];
    int lane = tid & 31, w = tid >> 5;
    int ps = s;
#pragma unroll
    for (int o = 1; o < 32; o <<= 1) {
        int t = __shfl_up_sync(0xffffffffu, ps, o);
        if (lane >= o) ps += t;
    }
    if (lane == 31) wsum[w] = ps;
    __syncthreads();
    if (w == 0) {
        int t = (lane < 8) ? wsum[lane] : 0;
#pragma unroll
        for (int o = 1; o < 8; o <<= 1) {
            int u = __shfl_up_sync(0xffffffffu, t, o);
            if (lane >= o) t += u;
        }
        if (lane < 8) wsum[lane] = t;
    }
    __syncthreads();
    int run = ps - s + (w ? wsum[w - 1] : 0);   // block-local exclusive
#pragma unroll
    for (int j = 0; j < 4; j++) {
        int i = base + j;
        if (i < n) g_off[i] = run;
        else if (i == n) g_off[n] = run;        // sentinel (block-local)
        run += v[j];
    }
    if (tid == 0) g_bsums[blockIdx.x] = wsum[7];

    // last-block cross-scan of g_bsums
    __threadfence();
    if (tid == 0) {
        int old = atomicAdd(&g_done, 1);
        isLast = (old == nb - 1);
    }
    __syncthreads();
    if (isLast) {
        int val = (tid < nb) ? ((volatile int*)g_bsums)[tid] : 0;
        sh[tid] = val;
        __syncthreads();
        for (int o = 1; o < 256; o <<= 1) {
            int t = (tid >= o) ? sh[tid - o] : 0;
            __syncthreads();
            sh[tid] += t;
            __syncthreads();
        }
        g_bsums[tid] = sh[tid] - val;           // exclusive
        if (tid == 0) g_done = 0;               // self-reset for next replay
    }
}

__global__ void k_scatter(const int* __restrict__ ei, int E) {
    int e = blockIdx.x * blockDim.x + threadIdx.x;
    if (e >= E) return;
    int s = ei[e];
    int d = ei[E + e];
    int pos = foff(d) + atomicAdd(&g_cur[d], 1);
    g_meta[pos] = make_int2(s, __float_as_int(g_dinv[s] * g_dinv[d]));
}

// re-zero atomically-accumulated buffers for the NEXT replay (runs on the side
// stream right after scatter; hidden under the layer pipeline, joined at end)
__global__ void k_reset(int n) {
    int i = blockIdx.x * blockDim.x + threadIdx.x;
    if (i < n) { g_deg[i] = 0; g_cur[i] = 0; }
}

// ---------------- packed f32x2 helpers ----------------
__device__ __forceinline__ unsigned long long dup2(float x) {
    unsigned long long r;
    asm("mov.b64 %0, {%1, %1};" : "=l"(r) : "f"(x));
    return r;
}
__device__ __forceinline__ void ffma2(unsigned long long& d,
                                      unsigned long long a, unsigned long long b) {
    asm("fma.rn.f32x2 %0, %1, %2, %0;" : "+l"(d) : "l"(a), "l"(b));
}
__device__ __forceinline__ float2 unpk(unsigned long long v) {
    float2 r;
    asm("mov.b64 {%0, %1}, %2;" : "=f"(r.x), "=f"(r.y) : "l"(v));
    return r;
}

// ---------------- GEMM: g_t[n,64](fp16) = A[n,K](fp32) @ W[K,64] -------------
// A == nullptr -> read g_h. 128x64 tile, 256 thr; accumulators pair ADJACENT
// ROWS (direct LDS.64 a-operand, fp32 math); epilogue converts to fp16.
template <int K>
__global__ __launch_bounds__(256) void k_gemm(const float* __restrict__ Ain,
                                              const float* __restrict__ W, int n) {
    const float* A = Ain ? Ain : g_h;
    constexpr int KC = 32;
    constexpr int PF = 2 * KC + 4;                   // 68 floats per pair-row
    __shared__ __align__(16) float Xs[64 * PF];      // [pair][2k + parity]
    __shared__ __align__(16) float Wsh[KC * 64];

    int tid = threadIdx.x;
    int row0 = blockIdx.x * 128;
    int tx = tid & 15, ty = tid >> 4;
    int c0 = tx * 4;
    int p0 = ty * 4;                                 // first row-pair

    unsigned long long acc[4][4];                    // [row-pair][col]
#pragma unroll
    for (int i = 0; i < 4; i++)
#pragma unroll
        for (int j = 0; j < 4; j++) acc[i][j] = 0ull;

    for (int kc = 0; kc < K; kc += KC) {
        __syncthreads();
#pragma unroll
        for (int it = 0; it < 4; ++it) {
            int i = tid + it * 256;          // 1024 float4 slots
            int row = i >> 3;
            int k4 = (i & 7) * 4;
            int gr = row0 + row;
            float4 v = make_float4(0.f, 0.f, 0.f, 0.f);
            if (gr < n) v = *(const float4*)&A[(size_t)gr * K + kc + k4];
            int base = (row >> 1) * PF + (row & 1);
            Xs[base + 2 * (k4 + 0)] = v.x;
            Xs[base + 2 * (k4 + 1)] = v.y;
            Xs[base + 2 * (k4 + 2)] = v.z;
            Xs[base + 2 * (k4 + 3)] = v.w;
        }
#pragma unroll
        for (int it = 0; it < 2; ++it) {
            int i = tid + it * 256;
            *(float4*)&Wsh[i * 4] = *(const float4*)&W[(size_t)kc * 64 + i * 4];
        }
        __syncthreads();

#pragma unroll
        for (int k = 0; k < KC; ++k) {
            float4 wv = *(const float4*)&Wsh[k * 64 + c0];
            unsigned long long w0 = dup2(wv.x), w1 = dup2(wv.y);
            unsigned long long w2 = dup2(wv.z), w3 = dup2(wv.w);
#pragma unroll
            for (int i = 0; i < 4; i++) {
                unsigned long long x2 =
                    *(const unsigned long long*)&Xs[(p0 + i) * PF + 2 * k];
                ffma2(acc[i][0], x2, w0);
                ffma2(acc[i][1], x2, w1);
                ffma2(acc[i][2], x2, w2);
                ffma2(acc[i][3], x2, w3);
            }
        }
    }

#pragma unroll
    for (int i = 0; i < 4; i++) {
        int gr = row0 + (p0 + i) * 2;
        float2 a0 = unpk(acc[i][0]), a1 = unpk(acc[i][1]);
        float2 a2 = unpk(acc[i][2]), a3 = unpk(acc[i][3]);
        if (gr < n) {
            __half2 h01 = __floats2half2_rn(a0.x, a1.x);
            __half2 h23 = __floats2half2_rn(a2.x, a3.x);
            *(uint2*)&g_t[(size_t)gr * 64 + c0] =
                make_uint2(*(unsigned*)&h01, *(unsigned*)&h23);
        }
        if (gr + 1 < n) {
            __half2 h01 = __floats2half2_rn(a0.y, a1.y);
            __half2 h23 = __floats2half2_rn(a2.y, a3.y);
            *(uint2*)&g_t[(size_t)(gr + 1) * 64 + c0] =
                make_uint2(*(unsigned*)&h01, *(unsigned*)&h23);
        }
    }
}

// ---------------- propagation: out[d] = sum_{e: dst=d} w_e * t[src_e]
//                   + dinv[d]^2 * t[d] (+bias) (+relu), t in fp16 -------------
// Warp per node, lane owns one half2 (2 feats). Batch-8 gather: 8 independent
// LDGs in flight (MLP=8) + dual fp32 accumulator streams. Padded lanes carry
// w=0, s=0 (harmless row-0 load). No atomics.
__global__ __launch_bounds__(256) void k_prop(float* __restrict__ outp,
                                              const float* __restrict__ bias, int relu,
                                              int n) {
    float* out = outp ? outp : g_h;
    const __half2* t2 = (const __half2*)g_t;     // row = 32 half2
    int node = (blockIdx.x * blockDim.x + threadIdx.x) >> 5;
    int lane = threadIdx.x & 31;
    if (node >= n) return;
    int beg = foff(node), end = foff(node + 1);
    const __half2* tf = t2 + lane;

    float ax0 = 0.f, ay0 = 0.f, ax1 = 0.f, ay1 = 0.f;
    for (int j = beg; j < end; j += 32) {
        int m = end - j;
        if (m > 32) m = 32;
        int sv = 0;
        float wv = 0.f;
        if (lane < m) {
            int2 mw = g_meta[j + lane];
            sv = mw.x;
            wv = __int_as_float(mw.y);
        }
        int nb8 = (m + 7) >> 3;
        for (int b = 0; b < nb8; ++b) {
            int bb = b * 8;
            int s[8];
            float w[8];
            __half2 v[8];
#pragma unroll
            for (int i = 0; i < 8; i++) {
                s[i] = __shfl_sync(0xffffffffu, sv, bb + i);
                w[i] = __shfl_sync(0xffffffffu, wv, bb + i);
            }
#pragma unroll
            for (int i = 0; i < 8; i++) v[i] = tf[(size_t)s[i] * 32];
#pragma unroll
            for (int i = 0; i < 8; i++) {
                float2 f = __half22float2(v[i]);
                if (i & 1) { ax1 = fmaf(w[i], f.x, ax1); ay1 = fmaf(w[i], f.y, ay1); }
                else       { ax0 = fmaf(w[i], f.x, ax0); ay0 = fmaf(w[i], f.y, ay0); }
            }
        }
    }
    float accx = ax0 + ax1, accy = ay0 + ay1;
    // self loop
    float dv = g_dinv[node];
    float2 v0 = __half22float2(tf[(size_t)node * 32]);
    float w0 = dv * dv;
    accx = fmaf(w0, v0.x, accx);
    accy = fmaf(w0, v0.y, accy);
    if (bias) { accx += bias[2 * lane]; accy += bias[2 * lane + 1]; }
    if (relu) { accx = fmaxf(accx, 0.f); accy = fmaxf(accy, 0.f); }
    *(float2*)(out + (size_t)node * 64 + 2 * lane) = make_float2(accx, accy);
}

// ---------------- launch ----------------
extern "C" void kernel_launch(void* const* d_in, const int* in_sizes, int n_in,
                              void* d_out, int out_size) {
    const float* x     = (const float*)d_in[0];
    const int*   ei    = (const int*)d_in[1];     // int32 (JAX x64 disabled)
    const float* W_in  = (const float*)d_in[2];
    const float* b_in  = (const float*)d_in[3];
    const float* W_h   = (const float*)d_in[4];
    const float* b_h   = (const float*)d_in[5];
    const float* W_out = (const float*)d_in[6];

    int n = in_sizes[0] / 128;
    int E = in_sizes[1] / 2;

    int nb1 = (n + 1023) / 1024;
    int gb = (n + 127) / 128;
    int pb = (n + 7) / 8;

    // Fork: CSR build on side stream (init-free; relies on tail k_reset of the
    // previous replay / static zero-init on the first call).
    cudaEventRecord(g_evA, 0);
    cudaStreamWaitEvent(g_s2, g_evA, 0);
    k_count  <<<(E + 255) / 256, 256, 0, g_s2>>>(ei, E);     // slot 1
    k_scan1f <<<nb1, 256, 0, g_s2>>>(n, nb1);                // slot 2 (fused scan2)
    k_scatter<<<(E + 255) / 256, 256, 0, g_s2>>>(ei, E);     // slot 3
    cudaEventRecord(g_evB, g_s2);
    k_reset  <<<(n + 255) / 256, 256, 0, g_s2>>>(n);         // hidden tail work
    cudaEventRecord(g_evC, g_s2);                            // join handle

    // layer 1 GEMM overlaps the CSR build — code-slot 4 (ncu profile target)
    k_gemm<128><<<gb, 256>>>(x, W_in, n);

    // Join: prop needs both GEMM output and CSR
    cudaStreamWaitEvent(0, g_evB, 0);
    k_prop<<<pb, 256>>>(nullptr, b_in, 0, n);

    // hidden layers: h = relu(prop(h @ W_h[l]) + b_h[l])
    for (int l = 0; l < 3; ++l) {
        k_gemm<64><<<gb, 256>>>(nullptr, W_h + (size_t)l * 64 * 64, n);
        k_prop<<<pb, 256>>>(nullptr, b_h + (size_t)l * 64, 1, n);
    }

    // output layer: out = prop(h @ W_out), no bias, no relu
    k_gemm<64><<<gb, 256>>>(nullptr, W_out, n);
    k_prop<<<pb, 256>>>((float*)d_out, nullptr, 0, n);

    // Final join of the side stream (k_reset) so capture sees no unjoined work
    cudaStreamWaitEvent(0, g_evC, 0);
}